// round 1
// baseline (speedup 1.0000x reference)
#include <cuda_runtime.h>
#include <math.h>

// Problem constants
#define BATCH 4
#define NN    3000
#define FF    128

// ---------------- scratch (no allocations allowed) ----------------
__device__ float g_dis[BATCH * NN];          // d^{-1/2} per row
__device__ float g_xs [BATCH * NN * FF];     // dis_j * x[j,f]
__device__ float g_S  [BATCH * NN * FF];     // support

// ---------------- f32x2 packed-FMA helpers (sm_100+) ----------------
__device__ __forceinline__ unsigned long long pack_f32x2(float lo, float hi) {
    unsigned long long r;
    asm("mov.b64 %0, {%1, %2};" : "=l"(r) : "f"(lo), "f"(hi));
    return r;
}
__device__ __forceinline__ unsigned long long dup_f32x2(float v) {
    unsigned long long r;
    asm("mov.b64 %0, {%1, %1};" : "=l"(r) : "f"(v));
    return r;
}
__device__ __forceinline__ unsigned long long fma_f32x2(unsigned long long a,
                                                        unsigned long long b,
                                                        unsigned long long c) {
    unsigned long long d;
    asm("fma.rn.f32x2 %0, %1, %2, %3;" : "=l"(d) : "l"(a), "l"(b), "l"(c));
    return d;
}
__device__ __forceinline__ float2 unpack_f32x2(unsigned long long v) {
    float2 r;
    asm("mov.b64 {%0, %1}, %2;" : "=f"(r.x), "=f"(r.y) : "l"(v));
    return r;
}

// ---------------- Kernel 1: deg -> d^{-1/2} ----------------
// One block per (b, i) row of adj. deg = sum_j adj[i,j] + 1 (self loop).
__global__ __launch_bounds__(256) void k_rowstats(const float* __restrict__ adj) {
    int row = blockIdx.x;  // 0 .. BATCH*NN-1
    const float4* a4 = reinterpret_cast<const float4*>(adj + (size_t)row * NN);
    float s = 0.f;
    for (int i = threadIdx.x; i < NN / 4; i += 256) {
        float4 v = a4[i];
        s += (v.x + v.y) + (v.z + v.w);
    }
    #pragma unroll
    for (int o = 16; o > 0; o >>= 1) s += __shfl_down_sync(0xffffffffu, s, o);
    __shared__ float red[8];
    if ((threadIdx.x & 31) == 0) red[threadIdx.x >> 5] = s;
    __syncthreads();
    if (threadIdx.x == 0) {
        float t = 0.f;
        #pragma unroll
        for (int w = 0; w < 8; w++) t += red[w];
        g_dis[row] = rsqrtf(t + 1.0f);
    }
}

// ---------------- Kernel 2: xs = dis_j * x ----------------
__global__ __launch_bounds__(256) void k_xs(const float* __restrict__ x) {
    int idx = blockIdx.x * 256 + threadIdx.x;        // over float4s
    if (idx >= BATCH * NN * FF / 4) return;
    float4 v = reinterpret_cast<const float4*>(x)[idx];
    float d = g_dis[idx >> 5];                        // 32 float4 per row
    v.x *= d; v.y *= d; v.z *= d; v.w *= d;
    reinterpret_cast<float4*>(g_xs)[idx] = v;
}

// ---------------- Kernel 3: S = (1-a)*dis_i*(adj@xs + xs_i) + a*h0 ----------------
// Tiled SGEMM: BM=128, BN=128 (=F), BK=8, 256 threads, 8x8 micro-tile,
// packed f32x2 accumulators (row-pairs), register prefetch of next k-tile.
#define BM 128
#define BN 128
#define BK 8
__global__ __launch_bounds__(256) void k_agg(const float* __restrict__ adj,
                                             const float* __restrict__ h0g,
                                             const float* __restrict__ alpha_p) {
    int b  = blockIdx.y;
    int m0 = blockIdx.x * BM;
    const float* A  = adj  + (size_t)b * NN * NN;
    const float* Bx = g_xs + (size_t)b * NN * FF;

    __shared__ float As[BK][BM];
    __shared__ float Bs[BK][BN];

    int tid  = threadIdx.x;
    // global-load mapping
    int arow  = tid >> 1;          // 0..127
    int acol  = (tid & 1) * 4;     // 0 or 4
    int brow  = tid >> 5;          // 0..7
    int bcol  = (tid & 31) * 4;    // 0..124
    // compute mapping
    int tx = tid & 15;
    int ty = tid >> 4;
    int rbase = ty * 8;            // 0..120
    int cbase = tx * 8;            // 0..120

    bool a_ok = (m0 + arow) < NN;
    const float* aptr = A + (size_t)(m0 + arow) * NN + acol;

    unsigned long long accp[4][8];
    #pragma unroll
    for (int i2 = 0; i2 < 4; i2++)
        #pragma unroll
        for (int j = 0; j < 8; j++) accp[i2][j] = 0ull;

    // preload tile 0
    float4 av = a_ok ? *reinterpret_cast<const float4*>(aptr)
                     : make_float4(0.f, 0.f, 0.f, 0.f);
    float4 bv = *reinterpret_cast<const float4*>(Bx + brow * FF + bcol);

    for (int k0 = 0; k0 < NN; k0 += BK) {
        // regs -> smem
        As[acol + 0][arow] = av.x;
        As[acol + 1][arow] = av.y;
        As[acol + 2][arow] = av.z;
        As[acol + 3][arow] = av.w;
        *reinterpret_cast<float4*>(&Bs[brow][bcol]) = bv;
        __syncthreads();

        // prefetch next tile
        int kn = k0 + BK;
        if (kn < NN) {
            av = a_ok ? *reinterpret_cast<const float4*>(aptr + kn)
                      : make_float4(0.f, 0.f, 0.f, 0.f);
            bv = *reinterpret_cast<const float4*>(Bx + (kn + brow) * FF + bcol);
        }

        #pragma unroll
        for (int k = 0; k < BK; ++k) {
            float4 a0 = *reinterpret_cast<const float4*>(&As[k][rbase]);
            float4 a1 = *reinterpret_cast<const float4*>(&As[k][rbase + 4]);
            float4 b0 = *reinterpret_cast<const float4*>(&Bs[k][cbase]);
            float4 b1 = *reinterpret_cast<const float4*>(&Bs[k][cbase + 4]);
            unsigned long long ap[4];
            ap[0] = pack_f32x2(a0.x, a0.y);
            ap[1] = pack_f32x2(a0.z, a0.w);
            ap[2] = pack_f32x2(a1.x, a1.y);
            ap[3] = pack_f32x2(a1.z, a1.w);
            float bsv[8] = {b0.x, b0.y, b0.z, b0.w, b1.x, b1.y, b1.z, b1.w};
            #pragma unroll
            for (int j = 0; j < 8; j++) {
                unsigned long long bd = dup_f32x2(bsv[j]);
                #pragma unroll
                for (int i2 = 0; i2 < 4; i2++)
                    accp[i2][j] = fma_f32x2(ap[i2], bd, accp[i2][j]);
            }
        }
        __syncthreads();
    }

    // epilogue: support
    float alpha = alpha_p[0];
    float oma   = 1.0f - alpha;

    #pragma unroll
    for (int i2 = 0; i2 < 4; i2++) {
        float lo[8], hi[8];
        #pragma unroll
        for (int j = 0; j < 8; j++) {
            float2 v = unpack_f32x2(accp[i2][j]);
            lo[j] = v.x; hi[j] = v.y;
        }
        #pragma unroll
        for (int h = 0; h < 2; h++) {
            int r = m0 + rbase + 2 * i2 + h;
            if (r < NN) {
                float di = g_dis[b * NN + r];
                size_t base = ((size_t)b * NN + r) * FF + cbase;
                float4 xs0 = *reinterpret_cast<const float4*>(g_xs + base);
                float4 xs1 = *reinterpret_cast<const float4*>(g_xs + base + 4);
                float4 hv0 = *reinterpret_cast<const float4*>(h0g + base);
                float4 hv1 = *reinterpret_cast<const float4*>(h0g + base + 4);
                float v0 = h ? hi[0] : lo[0]; float v1 = h ? hi[1] : lo[1];
                float v2 = h ? hi[2] : lo[2]; float v3 = h ? hi[3] : lo[3];
                float v4 = h ? hi[4] : lo[4]; float v5 = h ? hi[5] : lo[5];
                float v6 = h ? hi[6] : lo[6]; float v7 = h ? hi[7] : lo[7];
                float4 o0, o1;
                o0.x = oma * di * (v0 + xs0.x) + alpha * hv0.x;
                o0.y = oma * di * (v1 + xs0.y) + alpha * hv0.y;
                o0.z = oma * di * (v2 + xs0.z) + alpha * hv0.z;
                o0.w = oma * di * (v3 + xs0.w) + alpha * hv0.w;
                o1.x = oma * di * (v4 + xs1.x) + alpha * hv1.x;
                o1.y = oma * di * (v5 + xs1.y) + alpha * hv1.y;
                o1.z = oma * di * (v6 + xs1.z) + alpha * hv1.z;
                o1.w = oma * di * (v7 + xs1.w) + alpha * hv1.w;
                *reinterpret_cast<float4*>(g_S + base)     = o0;
                *reinterpret_cast<float4*>(g_S + base + 4) = o1;
            }
        }
    }
}

// ---------------- Kernel 4: out = beta * (S @ theta) + (1-beta) * S ----------------
// 16 rows per block, 256 threads (2 threads per output column, 8 rows each).
__global__ __launch_bounds__(256) void k_out(const float* __restrict__ theta,
                                             const float* __restrict__ lamda_p,
                                             const int* __restrict__ l_p,
                                             float* __restrict__ out) {
    __shared__ float Ss[16][FF];
    int row0 = blockIdx.x * 16;       // global row in [0, BATCH*NN)
    int tid  = threadIdx.x;

    const float4* S4 = reinterpret_cast<const float4*>(g_S + (size_t)row0 * FF);
    float4* Ss4 = reinterpret_cast<float4*>(&Ss[0][0]);
    Ss4[tid]       = S4[tid];
    Ss4[tid + 256] = S4[tid + 256];
    __syncthreads();

    float beta = logf(lamda_p[0] / (float)l_p[0] + 1.0f);
    float omb  = 1.0f - beta;

    int g  = tid & 127;
    int r0 = (tid >> 7) * 8;

    float acc[8];
    #pragma unroll
    for (int i = 0; i < 8; i++) acc[i] = 0.f;

    #pragma unroll 4
    for (int f = 0; f < FF; ++f) {
        float th = __ldg(theta + f * FF + g);
        #pragma unroll
        for (int i = 0; i < 8; i++) acc[i] += Ss[r0 + i][f] * th;
    }

    #pragma unroll
    for (int i = 0; i < 8; i++) {
        int rr = r0 + i;
        out[((size_t)row0 + rr) * FF + g] = beta * acc[i] + omb * Ss[rr][g];
    }
}

// ---------------- launch ----------------
extern "C" void kernel_launch(void* const* d_in, const int* in_sizes, int n_in,
                              void* d_out, int out_size) {
    const float* x     = (const float*)d_in[0];
    const float* adj   = (const float*)d_in[1];
    const float* h0    = (const float*)d_in[2];
    const float* theta = (const float*)d_in[3];
    const float* lamda = (const float*)d_in[4];
    const float* alpha = (const float*)d_in[5];
    const int*   lptr  = (const int*)  d_in[6];

    k_rowstats<<<BATCH * NN, 256>>>(adj);
    k_xs<<<(BATCH * NN * FF / 4 + 255) / 256, 256>>>(x);
    dim3 g3((NN + BM - 1) / BM, BATCH);
    k_agg<<<g3, 256>>>(adj, h0, alpha);
    k_out<<<BATCH * NN / 16, 256>>>(theta, lamda, lptr, (float*)d_out);
}

// round 3
// speedup vs baseline: 2.1559x; 2.1559x over previous
#include <cuda_runtime.h>
#include <math.h>

// Problem constants
#define BATCH 4
#define NN    3000
#define FF    128

// ---------------- scratch (no allocations allowed) ----------------
__device__ float g_dis[BATCH * NN];          // d^{-1/2} per row
__device__ float g_xs [BATCH * NN * FF];     // dis_j * x[j,f]
__device__ float g_S  [BATCH * NN * FF];     // support

// ---------------- tf32 helper ----------------
__device__ __forceinline__ unsigned f2tf(float f) {
    unsigned u;
    asm("cvt.rna.tf32.f32 %0, %1;" : "=r"(u) : "f"(f));
    return u;
}

// ---------------- Kernel 1: deg -> d^{-1/2}, and xs = dis_j * x[j,:] ----------------
__global__ __launch_bounds__(256) void k_rowstats(const float* __restrict__ adj,
                                                  const float* __restrict__ x) {
    int row = blockIdx.x;  // 0 .. BATCH*NN-1
    const float4* a4 = reinterpret_cast<const float4*>(adj + (size_t)row * NN);
    float s = 0.f;
    for (int i = threadIdx.x; i < NN / 4; i += 256) {
        float4 v = a4[i];
        s += (v.x + v.y) + (v.z + v.w);
    }
    #pragma unroll
    for (int o = 16; o > 0; o >>= 1) s += __shfl_down_sync(0xffffffffu, s, o);
    __shared__ float red[8];
    __shared__ float sdis;
    if ((threadIdx.x & 31) == 0) red[threadIdx.x >> 5] = s;
    __syncthreads();
    if (threadIdx.x == 0) {
        float t = 0.f;
        #pragma unroll
        for (int w = 0; w < 8; w++) t += red[w];
        float d = rsqrtf(t + 1.0f);
        g_dis[row] = d;
        sdis = d;
    }
    __syncthreads();
    if (threadIdx.x < FF / 4) {
        float d = sdis;
        float4 v = reinterpret_cast<const float4*>(x + (size_t)row * FF)[threadIdx.x];
        v.x *= d; v.y *= d; v.z *= d; v.w *= d;
        reinterpret_cast<float4*>(g_xs + (size_t)row * FF)[threadIdx.x] = v;
    }
}

// ---------------- Kernel 2: tensor-core aggregation ----------------
// S = (1-a) * dis_i * ((adj @ xs)_i + xs_i) + a * h0
// tf32 mma.sync m16n8k8.  BM=128, BN=FF=128, BK=16, 128 threads = 4 warps,
// warp tile 64x64 (2x2 warp grid), double-buffered smem, conflict-free pitches.
#define BM 128
#define BK 16

__global__ __launch_bounds__(128, 1) void k_agg(const float* __restrict__ adj,
                                                const float* __restrict__ h0g,
                                                const float* __restrict__ alpha_p) {
    // A tile: m-major, pitch 20 floats  (frag banks: (g*20+s)%32 all distinct)
    // B tile: k-major, pitch 136 floats (frag banks: (s*136+n)%32 = (s*8+n)%32 distinct)
    __shared__ float As[2][BM][20];
    __shared__ float Bs[2][BK][136];

    const int b  = blockIdx.y;
    const int m0 = blockIdx.x * BM;
    const float* A  = adj  + (size_t)b * NN * NN;
    const float* Bx = g_xs + (size_t)b * NN * FF;

    const int tid  = threadIdx.x;
    const int w    = tid >> 5;
    const int lane = tid & 31;
    const int g    = lane >> 2;   // groupID
    const int s    = lane & 3;    // threadID_in_group
    const int wm   = w >> 1;      // 0..1
    const int wn   = w & 1;       // 0..1

    float acc[4][8][4];
    #pragma unroll
    for (int mt = 0; mt < 4; mt++)
        #pragma unroll
        for (int nt = 0; nt < 8; nt++)
            #pragma unroll
            for (int r = 0; r < 4; r++) acc[mt][nt][r] = 0.f;

    // global-load staging registers
    float4 aR[4], bR[4];
    const int  arow = m0 + tid;
    const bool a_ok = arow < NN;
    const float* aptr = A + (size_t)arow * NN;

    const float4 z4 = make_float4(0.f, 0.f, 0.f, 0.f);

    // ---- load tile k0 into staging regs ----
    auto load_global = [&](int k0) {
        #pragma unroll
        for (int i = 0; i < 4; i++) {
            int k = k0 + i * 4;
            aR[i] = (a_ok && (k + 4 <= NN)) ? *reinterpret_cast<const float4*>(aptr + k) : z4;
        }
        #pragma unroll
        for (int i = 0; i < 4; i++) {
            int idx = i * 128 + tid;       // 0..511
            int r   = idx >> 5;            // 0..15
            int c4  = idx & 31;            // 0..31
            int kr  = k0 + r;
            bR[i] = (kr < NN) ? *reinterpret_cast<const float4*>(Bx + (size_t)kr * FF + c4 * 4) : z4;
        }
    };

    // ---- staging regs -> smem (with tf32 rounding) ----
    auto store_smem = [&](int buf) {
        #pragma unroll
        for (int i = 0; i < 4; i++) {
            float4 v = aR[i];
            float4 c;
            c.x = __uint_as_float(f2tf(v.x));
            c.y = __uint_as_float(f2tf(v.y));
            c.z = __uint_as_float(f2tf(v.z));
            c.w = __uint_as_float(f2tf(v.w));
            *reinterpret_cast<float4*>(&As[buf][tid][i * 4]) = c;
        }
        #pragma unroll
        for (int i = 0; i < 4; i++) {
            int idx = i * 128 + tid;
            int r   = idx >> 5;
            int c4  = idx & 31;
            float4 v = bR[i];
            float4 c;
            c.x = __uint_as_float(f2tf(v.x));
            c.y = __uint_as_float(f2tf(v.y));
            c.z = __uint_as_float(f2tf(v.z));
            c.w = __uint_as_float(f2tf(v.w));
            *reinterpret_cast<float4*>(&Bs[buf][r][c4 * 4]) = c;
        }
    };

    // ---- compute on one smem tile (two k8 substeps) ----
    auto compute = [&](int buf) {
        #pragma unroll
        for (int sub = 0; sub < 2; sub++) {
            int ks = sub * 8;
            unsigned af[4][4];
            #pragma unroll
            for (int mt = 0; mt < 4; mt++) {
                int rb = wm * 64 + mt * 16;
                af[mt][0] = __float_as_uint(As[buf][rb + g    ][ks + s    ]);
                af[mt][1] = __float_as_uint(As[buf][rb + g + 8][ks + s    ]);
                af[mt][2] = __float_as_uint(As[buf][rb + g    ][ks + s + 4]);
                af[mt][3] = __float_as_uint(As[buf][rb + g + 8][ks + s + 4]);
            }
            #pragma unroll
            for (int nt = 0; nt < 8; nt++) {
                int col = wn * 64 + nt * 8 + g;
                unsigned b0 = __float_as_uint(Bs[buf][ks + s    ][col]);
                unsigned b1 = __float_as_uint(Bs[buf][ks + s + 4][col]);
                #pragma unroll
                for (int mt = 0; mt < 4; mt++) {
                    asm volatile(
                        "mma.sync.aligned.m16n8k8.row.col.f32.tf32.tf32.f32 "
                        "{%0,%1,%2,%3}, {%4,%5,%6,%7}, {%8,%9}, {%0,%1,%2,%3};"
                        : "+f"(acc[mt][nt][0]), "+f"(acc[mt][nt][1]),
                          "+f"(acc[mt][nt][2]), "+f"(acc[mt][nt][3])
                        : "r"(af[mt][0]), "r"(af[mt][1]), "r"(af[mt][2]), "r"(af[mt][3]),
                          "r"(b0), "r"(b1));
                }
            }
        }
    };

    const int NT = (NN + BK - 1) / BK;   // 188 tiles (tail tile has 8 valid k)
    load_global(0);
    store_smem(0);
    __syncthreads();

    for (int t = 0; t < NT; t++) {
        int buf = t & 1;
        if (t + 1 < NT) load_global((t + 1) * BK);
        compute(buf);
        if (t + 1 < NT) store_smem(buf ^ 1);
        __syncthreads();
    }

    // ---- fused support epilogue ----
    float alpha = alpha_p[0];
    float oma   = 1.0f - alpha;

    #pragma unroll
    for (int mt = 0; mt < 4; mt++) {
        #pragma unroll
        for (int half = 0; half < 2; half++) {
            int r = m0 + wm * 64 + mt * 16 + g + half * 8;
            if (r < NN) {
                float di = g_dis[b * NN + r];
                size_t base = ((size_t)b * NN + r) * FF;
                #pragma unroll
                for (int nt = 0; nt < 8; nt++) {
                    int col = wn * 64 + nt * 8 + s * 2;
                    float2 xs = *reinterpret_cast<const float2*>(g_xs + base + col);
                    float2 hv = *reinterpret_cast<const float2*>(h0g + base + col);
                    float c0 = acc[mt][nt][half * 2 + 0];
                    float c1 = acc[mt][nt][half * 2 + 1];
                    float2 o;
                    o.x = oma * di * (c0 + xs.x) + alpha * hv.x;
                    o.y = oma * di * (c1 + xs.y) + alpha * hv.y;
                    *reinterpret_cast<float2*>(g_S + base + col) = o;
                }
            }
        }
    }
}

// ---------------- Kernel 3: out = beta * (S @ theta) + (1-beta) * S ----------------
__global__ __launch_bounds__(256) void k_out(const float* __restrict__ theta,
                                             const float* __restrict__ lamda_p,
                                             const int* __restrict__ l_p,
                                             float* __restrict__ out) {
    __shared__ float Ss[16][FF];
    int row0 = blockIdx.x * 16;       // global row in [0, BATCH*NN)
    int tid  = threadIdx.x;

    const float4* S4 = reinterpret_cast<const float4*>(g_S + (size_t)row0 * FF);
    float4* Ss4 = reinterpret_cast<float4*>(&Ss[0][0]);
    Ss4[tid]       = S4[tid];
    Ss4[tid + 256] = S4[tid + 256];
    __syncthreads();

    float beta = logf(lamda_p[0] / (float)l_p[0] + 1.0f);
    float omb  = 1.0f - beta;

    int g  = tid & 127;
    int r0 = (tid >> 7) * 8;

    float acc[8];
    #pragma unroll
    for (int i = 0; i < 8; i++) acc[i] = 0.f;

    #pragma unroll 4
    for (int f = 0; f < FF; ++f) {
        float th = __ldg(theta + f * FF + g);
        #pragma unroll
        for (int i = 0; i < 8; i++) acc[i] += Ss[r0 + i][f] * th;
    }

    #pragma unroll
    for (int i = 0; i < 8; i++) {
        int rr = r0 + i;
        out[((size_t)row0 + rr) * FF + g] = beta * acc[i] + omb * Ss[rr][g];
    }
}

// ---------------- launch ----------------
extern "C" void kernel_launch(void* const* d_in, const int* in_sizes, int n_in,
                              void* d_out, int out_size) {
    const float* x     = (const float*)d_in[0];
    const float* adj   = (const float*)d_in[1];
    const float* h0    = (const float*)d_in[2];
    const float* theta = (const float*)d_in[3];
    const float* lamda = (const float*)d_in[4];
    const float* alpha = (const float*)d_in[5];
    const int*   lptr  = (const int*)  d_in[6];

    k_rowstats<<<BATCH * NN, 256>>>(adj, x);
    dim3 g3((NN + BM - 1) / BM, BATCH);
    k_agg<<<g3, 128>>>(adj, h0, alpha);
    k_out<<<BATCH * NN / 16, 256>>>(theta, lamda, lptr, (float*)d_out);
}

// round 5
// speedup vs baseline: 4.7012x; 2.1807x over previous
#include <cuda_runtime.h>
#include <cstdint>
#include <math.h>

// Problem constants
#define BATCH 4
#define NN    3000
#define FF    128

// ---------------- scratch (no allocations allowed) ----------------
__device__ __align__(128) float g_dis[BATCH * NN];        // d^{-1/2}
__device__ __align__(128) float g_xs [BATCH * NN * FF];   // dis_j * x[j,f]

// ---------------- helpers ----------------
__device__ __forceinline__ uint32_t smem_u32(const void* p) {
    uint32_t a;
    asm("{ .reg .u64 t; cvta.to.shared.u64 t, %1; cvt.u32.u64 %0, t; }" : "=r"(a) : "l"(p));
    return a;
}
__device__ __forceinline__ unsigned f2tf(float f) {
    unsigned u;
    asm("cvt.rna.tf32.f32 %0, %1;" : "=r"(u) : "f"(f));
    return u;
}
__device__ __forceinline__ void cp16(uint32_t dst, const void* src, int bytes) {
    asm volatile("cp.async.cg.shared.global [%0], [%1], 16, %2;"
                 :: "r"(dst), "l"(src), "r"(bytes));
}
__device__ __forceinline__ void cp_commit() { asm volatile("cp.async.commit_group;" ::: "memory"); }

__device__ __forceinline__ void mma_tf32_frag(float* c, const unsigned* a, unsigned b0, unsigned b1) {
    asm volatile(
        "mma.sync.aligned.m16n8k8.row.col.f32.tf32.tf32.f32 "
        "{%0,%1,%2,%3}, {%4,%5,%6,%7}, {%8,%9}, {%0,%1,%2,%3};"
        : "+f"(c[0]), "+f"(c[1]), "+f"(c[2]), "+f"(c[3])
        : "r"(a[0]), "r"(a[1]), "r"(a[2]), "r"(a[3]), "r"(b0), "r"(b1));
}

// ---------------- Kernel 1: deg -> d^{-1/2}, xs = dis_j * x[j,:] ----------------
__global__ __launch_bounds__(256) void k_rowstats(const float* __restrict__ adj,
                                                  const float* __restrict__ x) {
    int row = blockIdx.x;
    const float4* a4 = reinterpret_cast<const float4*>(adj + (size_t)row * NN);
    float s0 = 0.f, s1 = 0.f;
    for (int i = threadIdx.x; i < NN / 4; i += 512) {
        float4 v = a4[i];
        s0 += (v.x + v.y) + (v.z + v.w);
        int i2 = i + 256;
        if (i2 < NN / 4) {
            float4 w = a4[i2];
            s1 += (w.x + w.y) + (w.z + w.w);
        }
    }
    float s = s0 + s1;
    #pragma unroll
    for (int o = 16; o > 0; o >>= 1) s += __shfl_down_sync(0xffffffffu, s, o);
    __shared__ float red[8];
    __shared__ float sdis;
    if ((threadIdx.x & 31) == 0) red[threadIdx.x >> 5] = s;
    __syncthreads();
    if (threadIdx.x == 0) {
        float t = 0.f;
        #pragma unroll
        for (int w = 0; w < 8; w++) t += red[w];
        float d = rsqrtf(t + 1.0f);
        g_dis[row] = d;
        sdis = d;
    }
    __syncthreads();
    if (threadIdx.x < FF / 4) {
        float d = sdis;
        float4 v = reinterpret_cast<const float4*>(x + (size_t)row * FF)[threadIdx.x];
        v.x *= d; v.y *= d; v.z *= d; v.w *= d;
        reinterpret_cast<float4*>(g_xs + (size_t)row * FF)[threadIdx.x] = v;
    }
}

// ---------------- Kernel 2: fully fused aggregation + output ----------------
// D   = adj_tile(96 x K) @ xs        (tf32 mma, cp.async 3-stage pipeline)
// S   = (1-a) * dis_i * (D + xs_i) + a * h0          (fp32, staged in smem)
// out = beta * (S @ theta) + (1-beta) * S            (second tf32 mma + fp32 blend)
#define BMM    96
#define BKK    32
#define NT     ((NN + BKK - 1) / BKK)     // 94
#define APITCH 36                          // floats; (36g+s)%32 = (4g+s)%32 distinct
#define BPITCH 136                         // floats; (136s+col)%32 = (8s+col)%32 distinct
#define S2PITCH 132                        // floats; (132g+s)%32 = (4g+s)%32 distinct

#define TH_F     (128 * BPITCH)            // 17408 floats (theta tile)
#define AS_STG_F (BMM * APITCH)            // 3456
#define BS_STG_F (BKK * BPITCH)            // 4352
#define AS_OFF_F TH_F
#define BS_OFF_F (AS_OFF_F + 3 * AS_STG_F)
#define S2_OFF_F AS_OFF_F                  // reuse pipeline buffers (12672 <= 23424 floats)
#define SMEM_F   (BS_OFF_F + 3 * BS_STG_F) // 40832 floats = 163328 bytes

__global__ __launch_bounds__(256, 1)
void k_agg(const float* __restrict__ adj,
           const float* __restrict__ h0g,
           const float* __restrict__ theta,
           const float* __restrict__ lamda_p,
           const float* __restrict__ alpha_p,
           const int* __restrict__ l_p,
           float* __restrict__ out) {
    extern __shared__ __align__(16) float dsm[];

    const int b   = blockIdx.y;
    const int m0  = blockIdx.x * BMM;
    const int tid = threadIdx.x;
    const int wid = tid >> 5, lane = tid & 31;
    const int g   = lane >> 2, s = lane & 3;
    const int wm  = wid >> 2;      // 0..1  -> 48-row half
    const int wn  = wid & 3;       // 0..3  -> 32-col quarter

    const uint32_t sb0 = smem_u32(dsm);
    const float* Ab = adj  + (size_t)b * NN * NN;
    const float* Bx = g_xs + (size_t)b * NN * FF;

    // ---- theta -> smem (its own cp.async group; completes early) ----
    #pragma unroll
    for (int c = 0; c < 16; c++) {
        int ch = c * 256 + tid;        // 0..4095
        int row = ch >> 5, nc = ch & 31;
        cp16(sb0 + (uint32_t)(row * BPITCH + nc * 4) * 4u, theta + row * FF + nc * 4, 16);
    }
    cp_commit();

    // ---- tile loader ----
    auto load_tile = [&](int t) {
        int k0 = t * BKK;
        uint32_t sa = sb0 + (uint32_t)(AS_OFF_F + (t % 3) * AS_STG_F) * 4u;
        #pragma unroll
        for (int c = 0; c < 3; c++) {
            int ch = c * 256 + tid;    // 0..767
            int row = ch >> 3, kc = ch & 7;
            int gr = m0 + row;
            int kk = k0 + kc * 4;
            int bytes = 16;
            if (gr >= NN) bytes = 0;
            int rem = (NN - kk) * 4;
            if (rem < 16) bytes = (rem > 0) ? (bytes < rem ? bytes : rem) : 0;
            const float* src = Ab + (size_t)(gr < NN ? gr : 0) * NN + (kk < NN ? kk : 0);
            cp16(sa + (uint32_t)(row * APITCH + kc * 4) * 4u, src, bytes);
        }
        uint32_t sbB = sb0 + (uint32_t)(BS_OFF_F + (t % 3) * BS_STG_F) * 4u;
        #pragma unroll
        for (int c = 0; c < 4; c++) {
            int ch = c * 256 + tid;    // 0..1023
            int row = ch >> 5, nc = ch & 31;
            int kr = k0 + row;
            int bytes = (kr < NN) ? 16 : 0;
            const float* src = Bx + (size_t)(kr < NN ? kr : 0) * FF + nc * 4;
            cp16(sbB + (uint32_t)(row * BPITCH + nc * 4) * 4u, src, bytes);
        }
    };

    float acc[3][4][4];
    #pragma unroll
    for (int mt = 0; mt < 3; mt++)
        #pragma unroll
        for (int nt = 0; nt < 4; nt++)
            #pragma unroll
            for (int r = 0; r < 4; r++) acc[mt][nt][r] = 0.f;

    load_tile(0); cp_commit();
    load_tile(1); cp_commit();

    for (int t = 0; t < NT; t++) {
        if (t + 2 < NT) load_tile(t + 2);
        cp_commit();
        asm volatile("cp.async.wait_group 2;" ::: "memory");
        __syncthreads();

        const float* As = dsm + AS_OFF_F + (t % 3) * AS_STG_F;
        const float* Bs = dsm + BS_OFF_F + (t % 3) * BS_STG_F;
        #pragma unroll
        for (int sub = 0; sub < 4; sub++) {
            int ks = sub * 8;
            unsigned af[3][4];
            #pragma unroll
            for (int mt = 0; mt < 3; mt++) {
                int rb = wm * 48 + mt * 16;
                af[mt][0] = f2tf(As[(rb + g    ) * APITCH + ks + s    ]);
                af[mt][1] = f2tf(As[(rb + g + 8) * APITCH + ks + s    ]);
                af[mt][2] = f2tf(As[(rb + g    ) * APITCH + ks + s + 4]);
                af[mt][3] = f2tf(As[(rb + g + 8) * APITCH + ks + s + 4]);
            }
            #pragma unroll
            for (int nt = 0; nt < 4; nt++) {
                int col = wn * 32 + nt * 8 + g;
                unsigned b0 = f2tf(Bs[(ks + s    ) * BPITCH + col]);
                unsigned b1 = f2tf(Bs[(ks + s + 4) * BPITCH + col]);
                #pragma unroll
                for (int mt = 0; mt < 3; mt++)
                    mma_tf32_frag(acc[mt][nt], af[mt], b0, b1);
            }
        }
        __syncthreads();
    }

    // ---- support epilogue into smem S tile (fp32) ----
    const float alpha = alpha_p[0];
    const float oma   = 1.0f - alpha;
    float* S2 = dsm + S2_OFF_F;

    #pragma unroll
    for (int mt = 0; mt < 3; mt++) {
        #pragma unroll
        for (int half = 0; half < 2; half++) {
            int r  = wm * 48 + mt * 16 + g + half * 8;   // local row 0..95
            int gr = m0 + r;
            bool ok = gr < NN;
            float di = ok ? g_dis[b * NN + gr] : 0.f;
            size_t base = ((size_t)b * NN + (ok ? gr : 0)) * FF;
            #pragma unroll
            for (int nt = 0; nt < 4; nt++) {
                int col = wn * 32 + nt * 8 + s * 2;
                float2 xsv = ok ? *reinterpret_cast<const float2*>(g_xs + base + col)
                                : make_float2(0.f, 0.f);
                float2 hv  = ok ? *reinterpret_cast<const float2*>(h0g + base + col)
                                : make_float2(0.f, 0.f);
                float c0 = acc[mt][nt][half * 2 + 0];
                float c1 = acc[mt][nt][half * 2 + 1];
                S2[r * S2PITCH + col    ] = oma * di * (c0 + xsv.x) + alpha * hv.x;
                S2[r * S2PITCH + col + 1] = oma * di * (c1 + xsv.y) + alpha * hv.y;
            }
        }
    }
    asm volatile("cp.async.wait_group 0;" ::: "memory");  // theta resident
    __syncthreads();

    // ---- second GEMM: D2 = S @ theta  (K = 128, theta smem k-major) ----
    float acc2[3][4][4];
    #pragma unroll
    for (int mt = 0; mt < 3; mt++)
        #pragma unroll
        for (int nt = 0; nt < 4; nt++)
            #pragma unroll
            for (int r = 0; r < 4; r++) acc2[mt][nt][r] = 0.f;

    const float* TH = dsm;   // theta tile, pitch BPITCH
    #pragma unroll 4
    for (int sub = 0; sub < 16; sub++) {
        int ks = sub * 8;
        unsigned af[3][4];
        #pragma unroll
        for (int mt = 0; mt < 3; mt++) {
            int rb = wm * 48 + mt * 16;
            af[mt][0] = __float_as_uint(S2[(rb + g    ) * S2PITCH + ks + s    ]);
            af[mt][1] = __float_as_uint(S2[(rb + g + 8) * S2PITCH + ks + s    ]);
            af[mt][2] = __float_as_uint(S2[(rb + g    ) * S2PITCH + ks + s + 4]);
            af[mt][3] = __float_as_uint(S2[(rb + g + 8) * S2PITCH + ks + s + 4]);
        }
        #pragma unroll
        for (int nt = 0; nt < 4; nt++) {
            int col = wn * 32 + nt * 8 + g;
            unsigned b0 = __float_as_uint(TH[(ks + s    ) * BPITCH + col]);
            unsigned b1 = __float_as_uint(TH[(ks + s + 4) * BPITCH + col]);
            #pragma unroll
            for (int mt = 0; mt < 3; mt++)
                mma_tf32_frag(acc2[mt][nt], af[mt], b0, b1);
        }
    }

    // ---- final blend + store:  out = beta * D2 + (1-beta) * S ----
    const float beta = logf(lamda_p[0] / (float)l_p[0] + 1.0f);
    const float omb  = 1.0f - beta;

    #pragma unroll
    for (int mt = 0; mt < 3; mt++) {
        #pragma unroll
        for (int half = 0; half < 2; half++) {
            int r  = wm * 48 + mt * 16 + g + half * 8;
            int gr = m0 + r;
            if (gr < NN) {
                size_t base = ((size_t)b * NN + gr) * FF;
                #pragma unroll
                for (int nt = 0; nt < 4; nt++) {
                    int col = wn * 32 + nt * 8 + s * 2;
                    float2 o;
                    o.x = beta * acc2[mt][nt][half * 2 + 0] + omb * S2[r * S2PITCH + col    ];
                    o.y = beta * acc2[mt][nt][half * 2 + 1] + omb * S2[r * S2PITCH + col + 1];
                    *reinterpret_cast<float2*>(out + base + col) = o;
                }
            }
        }
    }
}

// ---------------- launch ----------------
extern "C" void kernel_launch(void* const* d_in, const int* in_sizes, int n_in,
                              void* d_out, int out_size) {
    const float* x     = (const float*)d_in[0];
    const float* adj   = (const float*)d_in[1];
    const float* h0    = (const float*)d_in[2];
    const float* theta = (const float*)d_in[3];
    const float* lamda = (const float*)d_in[4];
    const float* alpha = (const float*)d_in[5];
    const int*   lptr  = (const int*)  d_in[6];

    cudaFuncSetAttribute(k_agg, cudaFuncAttributeMaxDynamicSharedMemorySize,
                         SMEM_F * 4);

    k_rowstats<<<BATCH * NN, 256>>>(adj, x);
    dim3 g3((NN + BMM - 1) / BMM, BATCH);
    k_agg<<<g3, 256, SMEM_F * 4>>>(adj, h0, theta, lamda, alpha, lptr, (float*)d_out);
}

// round 9
// speedup vs baseline: 4.9328x; 1.0493x over previous
#include <cuda_runtime.h>
#include <cstdint>
#include <math.h>

// Problem constants
#define BATCH 4
#define NN    3000
#define FF    128

// ---------------- scratch (no allocations allowed) ----------------
__device__ __align__(128) float g_dis[BATCH * NN];        // d^{-1/2}
__device__ __align__(128) float g_xs [BATCH * NN * FF];   // tf32-rounded dis_j * x[j,f]

// ---------------- helpers ----------------
__device__ __forceinline__ uint32_t smem_u32(const void* p) {
    uint32_t a;
    asm("{ .reg .u64 t; cvta.to.shared.u64 t, %1; cvt.u32.u64 %0, t; }" : "=r"(a) : "l"(p));
    return a;
}
__device__ __forceinline__ unsigned f2tf(float f) {
    unsigned u;
    asm("cvt.rna.tf32.f32 %0, %1;" : "=r"(u) : "f"(f));
    return u;
}
__device__ __forceinline__ void cp16(uint32_t dst, const void* src, int bytes) {
    asm volatile("cp.async.cg.shared.global [%0], [%1], 16, %2;"
                 :: "r"(dst), "l"(src), "r"(bytes));
}
__device__ __forceinline__ void cp_commit() { asm volatile("cp.async.commit_group;" ::: "memory"); }

__device__ __forceinline__ void mma_tf32_frag(float* c, const unsigned* a, unsigned b0, unsigned b1) {
    asm volatile(
        "mma.sync.aligned.m16n8k8.row.col.f32.tf32.tf32.f32 "
        "{%0,%1,%2,%3}, {%4,%5,%6,%7}, {%8,%9}, {%0,%1,%2,%3};"
        : "+f"(c[0]), "+f"(c[1]), "+f"(c[2]), "+f"(c[3])
        : "r"(a[0]), "r"(a[1]), "r"(a[2]), "r"(a[3]), "r"(b0), "r"(b1));
}

// ---------------- Kernel 1: deg -> d^{-1/2}, xs = tf32(dis_j * x[j,:]) ----------------
__global__ __launch_bounds__(256) void k_rowstats(const float* __restrict__ adj,
                                                  const float* __restrict__ x) {
    int row = blockIdx.x;
    const float4* a4 = reinterpret_cast<const float4*>(adj + (size_t)row * NN);
    float s0 = 0.f, s1 = 0.f;
    for (int i = threadIdx.x; i < NN / 4; i += 512) {
        float4 v = a4[i];
        s0 += (v.x + v.y) + (v.z + v.w);
        int i2 = i + 256;
        if (i2 < NN / 4) {
            float4 w = a4[i2];
            s1 += (w.x + w.y) + (w.z + w.w);
        }
    }
    float s = s0 + s1;
    #pragma unroll
    for (int o = 16; o > 0; o >>= 1) s += __shfl_down_sync(0xffffffffu, s, o);
    __shared__ float red[8];
    __shared__ float sdis;
    if ((threadIdx.x & 31) == 0) red[threadIdx.x >> 5] = s;
    __syncthreads();
    if (threadIdx.x == 0) {
        float t = 0.f;
        #pragma unroll
        for (int w = 0; w < 8; w++) t += red[w];
        float d = rsqrtf(t + 1.0f);
        g_dis[row] = d;
        sdis = d;
    }
    __syncthreads();
    if (threadIdx.x < FF / 4) {
        float d = sdis;
        float4 v = reinterpret_cast<const float4*>(x + (size_t)row * FF)[threadIdx.x];
        // tf32-round here so the GEMM B side needs no per-fragment cvt
        v.x = __uint_as_float(f2tf(v.x * d));
        v.y = __uint_as_float(f2tf(v.y * d));
        v.z = __uint_as_float(f2tf(v.z * d));
        v.w = __uint_as_float(f2tf(v.w * d));
        reinterpret_cast<float4*>(g_xs + (size_t)row * FF)[threadIdx.x] = v;
    }
}

// ---------------- Kernel 2: fully fused aggregation + output ----------------
// D   = adj_tile(96 x K) @ xs        (tf32 mma, cp.async 4-stage pipeline)
// S   = (1-a) * dis_i * (D + xs_i) + a * h0          (fp32, staged in smem)
// out = beta * (S @ theta) + (1-beta) * S            (second tf32 mma + fp32 blend)
#define BMM     96
#define BKK     32
#define NT      ((NN + BKK - 1) / BKK)     // 94
#define STAGES  4
#define APITCH  36                          // (4g+s)%32 distinct
#define BPITCH  136                         // (8s+col)%32 distinct
#define S2PITCH 132                         // (4g+s)%32 distinct

#define AS_STG_F (BMM * APITCH)             // 3456
#define BS_STG_F (BKK * BPITCH)             // 4352
#define AS_OFF_F 0
#define BS_OFF_F (STAGES * AS_STG_F)        // 13824
#define SMEM_F   (BS_OFF_F + STAGES * BS_STG_F)  // 31232 floats = 124928 B
// epilogue reuse: S2 at 0 (96*132=12672), theta at 12672 (128*136=17408) -> 30080 <= SMEM_F
#define S2_OFF_F 0
#define TH_OFF_F 12672

__global__ __launch_bounds__(256, 1)
void k_agg(const float* __restrict__ adj,
           const float* __restrict__ h0g,
           const float* __restrict__ theta,
           const float* __restrict__ lamda_p,
           const float* __restrict__ alpha_p,
           const int* __restrict__ l_p,
           float* __restrict__ out) {
    extern __shared__ __align__(16) float dsm[];

    const int b   = blockIdx.y;
    const int m0  = blockIdx.x * BMM;
    const int tid = threadIdx.x;
    const int wid = tid >> 5, lane = tid & 31;
    const int g   = lane >> 2, s = lane & 3;
    const int wm  = wid >> 2;      // 0..1  -> 48-row half
    const int wn  = wid & 3;       // 0..3  -> 32-col quarter

    const uint32_t sb0 = smem_u32(dsm);
    const float* Ab = adj  + (size_t)b * NN * NN;
    const float* Bx = g_xs + (size_t)b * NN * FF;

    // ---- tile loader ----
    auto load_tile = [&](int t) {
        int k0 = t * BKK;
        uint32_t sa = sb0 + (uint32_t)(AS_OFF_F + (t & 3) * AS_STG_F) * 4u;
        #pragma unroll
        for (int c = 0; c < 3; c++) {
            int ch = c * 256 + tid;    // 0..767
            int row = ch >> 3, kc = ch & 7;
            int gr = m0 + row;
            int kk = k0 + kc * 4;
            int bytes = 16;
            if (gr >= NN) bytes = 0;
            int rem = (NN - kk) * 4;
            if (rem < 16) bytes = (rem > 0) ? (bytes < rem ? bytes : rem) : 0;
            const float* src = Ab + (size_t)(gr < NN ? gr : 0) * NN + (kk < NN ? kk : 0);
            cp16(sa + (uint32_t)(row * APITCH + kc * 4) * 4u, src, bytes);
        }
        uint32_t sbB = sb0 + (uint32_t)(BS_OFF_F + (t & 3) * BS_STG_F) * 4u;
        #pragma unroll
        for (int c = 0; c < 4; c++) {
            int ch = c * 256 + tid;    // 0..1023
            int row = ch >> 5, nc = ch & 31;
            int kr = k0 + row;
            int bytes = (kr < NN) ? 16 : 0;
            const float* src = Bx + (size_t)(kr < NN ? kr : 0) * FF + nc * 4;
            cp16(sbB + (uint32_t)(row * BPITCH + nc * 4) * 4u, src, bytes);
        }
    };

    float acc[3][4][4];
    #pragma unroll
    for (int mt = 0; mt < 3; mt++)
        #pragma unroll
        for (int nt = 0; nt < 4; nt++)
            #pragma unroll
            for (int r = 0; r < 4; r++) acc[mt][nt][r] = 0.f;

    load_tile(0); cp_commit();
    load_tile(1); cp_commit();
    load_tile(2); cp_commit();

    // per-warp fragment base pointers
    const int rb0 = wm * 48;           // + mt*16
    const int cb0 = wn * 32;           // + nt*8 + g

    for (int t = 0; t < NT; t++) {
        if (t + 3 < NT) load_tile(t + 3);
        cp_commit();
        asm volatile("cp.async.wait_group 3;" ::: "memory");
        __syncthreads();

        const float* As = dsm + AS_OFF_F + (t & 3) * AS_STG_F;
        const float* Bs = dsm + BS_OFF_F + (t & 3) * BS_STG_F;

        // double-buffered fragments across the 4 k8 sub-steps
        unsigned af[2][3][4];
        unsigned bf[2][4][2];

        auto load_frag = [&](int sub, int buf) {
            int ks = sub * 8;
            #pragma unroll
            for (int mt = 0; mt < 3; mt++) {
                int rb = rb0 + mt * 16;
                af[buf][mt][0] = f2tf(As[(rb + g    ) * APITCH + ks + s    ]);
                af[buf][mt][1] = f2tf(As[(rb + g + 8) * APITCH + ks + s    ]);
                af[buf][mt][2] = f2tf(As[(rb + g    ) * APITCH + ks + s + 4]);
                af[buf][mt][3] = f2tf(As[(rb + g + 8) * APITCH + ks + s + 4]);
            }
            #pragma unroll
            for (int nt = 0; nt < 4; nt++) {
                int col = cb0 + nt * 8 + g;
                bf[buf][nt][0] = __float_as_uint(Bs[(ks + s    ) * BPITCH + col]);
                bf[buf][nt][1] = __float_as_uint(Bs[(ks + s + 4) * BPITCH + col]);
            }
        };

        load_frag(0, 0);
        #pragma unroll
        for (int sub = 0; sub < 4; sub++) {
            int cur = sub & 1;
            if (sub < 3) load_frag(sub + 1, cur ^ 1);
            #pragma unroll
            for (int nt = 0; nt < 4; nt++)
                #pragma unroll
                for (int mt = 0; mt < 3; mt++)
                    mma_tf32_frag(acc[mt][nt], af[cur][mt], bf[cur][nt][0], bf[cur][nt][1]);
        }
        __syncthreads();
    }

    // ---- theta -> smem (overlaps with support epilogue below) ----
    #pragma unroll
    for (int c = 0; c < 16; c++) {
        int ch = c * 256 + tid;        // 0..4095
        int row = ch >> 5, nc = ch & 31;
        cp16(sb0 + (uint32_t)(TH_OFF_F + row * BPITCH + nc * 4) * 4u,
             theta + row * FF + nc * 4, 16);
    }
    cp_commit();

    // ---- support epilogue into smem S tile (fp32) ----
    const float alpha = alpha_p[0];
    const float oma   = 1.0f - alpha;
    float* S2 = dsm + S2_OFF_F;

    #pragma unroll
    for (int mt = 0; mt < 3; mt++) {
        #pragma unroll
        for (int half = 0; half < 2; half++) {
            int r  = rb0 + mt * 16 + g + half * 8;       // local row 0..95
            int gr = m0 + r;
            bool ok = gr < NN;
            float di = ok ? g_dis[b * NN + gr] : 0.f;
            size_t base = ((size_t)b * NN + (ok ? gr : 0)) * FF;
            #pragma unroll
            for (int nt = 0; nt < 4; nt++) {
                int col = cb0 + nt * 8 + s * 2;
                float2 xsv = ok ? *reinterpret_cast<const float2*>(g_xs + base + col)
                                : make_float2(0.f, 0.f);
                float2 hv  = ok ? *reinterpret_cast<const float2*>(h0g + base + col)
                                : make_float2(0.f, 0.f);
                float c0 = acc[mt][nt][half * 2 + 0];
                float c1 = acc[mt][nt][half * 2 + 1];
                S2[r * S2PITCH + col    ] = oma * di * (c0 + xsv.x) + alpha * hv.x;
                S2[r * S2PITCH + col + 1] = oma * di * (c1 + xsv.y) + alpha * hv.y;
            }
        }
    }
    asm volatile("cp.async.wait_group 0;" ::: "memory");  // theta resident
    __syncthreads();

    // ---- second GEMM: D2 = S @ theta  (K = 128) ----
    float acc2[3][4][4];
    #pragma unroll
    for (int mt = 0; mt < 3; mt++)
        #pragma unroll
        for (int nt = 0; nt < 4; nt++)
            #pragma unroll
            for (int r = 0; r < 4; r++) acc2[mt][nt][r] = 0.f;

    const float* TH = dsm + TH_OFF_F;
    #pragma unroll 4
    for (int sub = 0; sub < 16; sub++) {
        int ks = sub * 8;
        unsigned af[3][4];
        #pragma unroll
        for (int mt = 0; mt < 3; mt++) {
            int rb = rb0 + mt * 16;
            af[mt][0] = __float_as_uint(S2[(rb + g    ) * S2PITCH + ks + s    ]);
            af[mt][1] = __float_as_uint(S2[(rb + g + 8) * S2PITCH + ks + s    ]);
            af[mt][2] = __float_as_uint(S2[(rb + g    ) * S2PITCH + ks + s + 4]);
            af[mt][3] = __float_as_uint(S2[(rb + g + 8) * S2PITCH + ks + s + 4]);
        }
        #pragma unroll
        for (int nt = 0; nt < 4; nt++) {
            int col = cb0 + nt * 8 + g;
            unsigned b0 = __float_as_uint(TH[(ks + s    ) * BPITCH + col]);
            unsigned b1 = __float_as_uint(TH[(ks + s + 4) * BPITCH + col]);
            #pragma unroll
            for (int mt = 0; mt < 3; mt++)
                mma_tf32_frag(acc2[mt][nt], af[mt], b0, b1);
        }
    }

    // ---- final blend + store:  out = beta * D2 + (1-beta) * S ----
    const float beta = logf(lamda_p[0] / (float)l_p[0] + 1.0f);
    const float omb  = 1.0f - beta;

    #pragma unroll
    for (int mt = 0; mt < 3; mt++) {
        #pragma unroll
        for (int half = 0; half < 2; half++) {
            int r  = rb0 + mt * 16 + g + half * 8;
            int gr = m0 + r;
            if (gr < NN) {
                size_t base = ((size_t)b * NN + gr) * FF;
                #pragma unroll
                for (int nt = 0; nt < 4; nt++) {
                    int col = cb0 + nt * 8 + s * 2;
                    float2 o;
                    o.x = beta * acc2[mt][nt][half * 2 + 0] + omb * S2[r * S2PITCH + col    ];
                    o.y = beta * acc2[mt][nt][half * 2 + 1] + omb * S2[r * S2PITCH + col + 1];
                    *reinterpret_cast<float2*>(out + base + col) = o;
                }
            }
        }
    }
}

// ---------------- launch ----------------
extern "C" void kernel_launch(void* const* d_in, const int* in_sizes, int n_in,
                              void* d_out, int out_size) {
    const float* x     = (const float*)d_in[0];
    const float* adj   = (const float*)d_in[1];
    const float* h0    = (const float*)d_in[2];
    const float* theta = (const float*)d_in[3];
    const float* lamda = (const float*)d_in[4];
    const float* alpha = (const float*)d_in[5];
    const int*   lptr  = (const int*)  d_in[6];

    cudaFuncSetAttribute(k_agg, cudaFuncAttributeMaxDynamicSharedMemorySize,
                         SMEM_F * 4);

    k_rowstats<<<BATCH * NN, 256>>>(adj, x);
    dim3 g3((NN + BMM - 1) / BMM, BATCH);
    k_agg<<<g3, 256, SMEM_F * 4>>>(adj, h0, theta, lamda, alpha, lptr, (float*)d_out);
}